// round 6
// baseline (speedup 1.0000x reference)
#include <cuda_runtime.h>
#include <math.h>

#define NREP 128
#define MNBR 48
#define NTH  256
#define ASTR 129          // A matrix shared stride (odd -> conflict-free column walks)
#define XSTR 130          // xsT shared stride (even -> float2 aligned)

// shared layout (float offsets)
#define OFF_A    0
#define OFF_X    16512    // 128*129
#define OFF_SCAL 22752    // +48*130
#define OFF_DIAG 22800
#define OFF_INVD 22928
#define SMEM_FLOATS 22960 // ~91.8 KB

__device__ __forceinline__ unsigned long long dup2(float x) {
    unsigned long long r;
    asm("mov.b64 %0, {%1, %1};" : "=l"(r) : "r"(__float_as_uint(x)));
    return r;
}
__device__ __forceinline__ unsigned long long pack2(float x, float y) {
    unsigned long long r;
    asm("mov.b64 %0, {%1, %2};" : "=l"(r) : "r"(__float_as_uint(x)), "r"(__float_as_uint(y)));
    return r;
}
__device__ __forceinline__ void unpack2(unsigned long long v, float &x, float &y) {
    unsigned lo, hi;
    asm("mov.b64 {%0, %1}, %2;" : "=r"(lo), "=r"(hi) : "l"(v));
    x = __uint_as_float(lo); y = __uint_as_float(hi);
}
// packed dual-FMA (sm_103a FFMA2) -- 2x fp32 throughput vs scalar FFMA
__device__ __forceinline__ void ffma2(unsigned long long &d, unsigned long long a, unsigned long long b) {
    asm("fma.rn.f32x2 %0, %1, %2, %3;" : "=l"(d) : "l"(a), "l"(b), "l"(d));
}

extern "C" __global__ void __launch_bounds__(NTH, 2)
tmap_kernel(const float* __restrict__ aug,
            const float* __restrict__ theta,
            const float* __restrict__ scales,
            const float* __restrict__ nug,
            const int*   __restrict__ bidx,
            float* __restrict__ out,
            int n_loc)
{
    extern __shared__ float sm[];
    float* Ash    = sm + OFF_A;
    float* XT     = sm + OFF_X;
    float* scal_s = sm + OFF_SCAL;
    float* diag_s = sm + OFF_DIAG;
    float* invd_s = sm + OFF_INVD;

    const int n   = blockIdx.x;
    const int tid = threadIdx.x;
    float* gout = out + (size_t)n * 16384;
    float* cout = out + (size_t)n_loc * 16384 + (size_t)n * 16384;

    // batch_idx == 0  ->  g = I, chol = I
    if (bidx[n] == 0) {
        for (int idx = tid; idx < 16384; idx += NTH) {
            float v = ((idx >> 7) == (idx & 127)) ? 1.0f : 0.0f;
            gout[idx] = v; cout[idx] = v;
        }
        return;
    }

    // ---- per-column scaling: scal_k = exp(-0.5*k*exp(theta2)), k=1..48 ----
    const float e2 = __expf(theta[2]);
    if (tid < MNBR) scal_s[tid] = __expf(-0.5f * (float)(tid + 1) * e2);
    __syncthreads();

    // ---- load xs transposed into shared: XT[k][r] = aug[r,n,k+1]*scal_k ----
    for (int idx = tid; idx < NREP * MNBR; idx += NTH) {
        int r = idx / MNBR, k = idx - r * MNBR;
        float v = aug[((size_t)r * n_loc + n) * (MNBR + 1) + 1 + k];
        if (v != v) v = 0.0f;  // NaN -> 0
        XT[k * XSTR + r] = v * scal_s[k];
    }
    __syncthreads();

    // ---- symmetric gram G = xs * xs^T : 3 lower 64x64 tiles, FFMA2, 4x4 microtiles
    {
        const int tx = tid & 15, ty = tid >> 4;
        const int TIs[3] = {0, 1, 1}, TJs[3] = {0, 0, 1};
        for (int t = 0; t < 3; ++t) {
            const int i0 = TIs[t] * 64 + ty * 4;
            const int j0 = TJs[t] * 64 + tx * 4;
            unsigned long long acc[4][2];
            #pragma unroll
            for (int r = 0; r < 4; ++r) { acc[r][0] = 0ull; acc[r][1] = 0ull; }
            #pragma unroll 8
            for (int k = 0; k < MNBR; ++k) {
                const float2* row = (const float2*)(XT + k * XSTR);
                float2 a01 = row[i0 >> 1];
                float2 a23 = row[(i0 >> 1) + 1];
                float2 b01 = row[j0 >> 1];
                float2 b23 = row[(j0 >> 1) + 1];
                unsigned long long bu0 = pack2(b01.x, b01.y);
                unsigned long long bu1 = pack2(b23.x, b23.y);
                unsigned long long a0 = dup2(a01.x), a1 = dup2(a01.y);
                unsigned long long a2 = dup2(a23.x), a3 = dup2(a23.y);
                ffma2(acc[0][0], a0, bu0); ffma2(acc[0][1], a0, bu1);
                ffma2(acc[1][0], a1, bu0); ffma2(acc[1][1], a1, bu1);
                ffma2(acc[2][0], a2, bu0); ffma2(acc[2][1], a2, bu1);
                ffma2(acc[3][0], a3, bu0); ffma2(acc[3][1], a3, bu1);
            }
            #pragma unroll
            for (int r = 0; r < 4; ++r) {
                float v0, v1, v2, v3;
                unpack2(acc[r][0], v0, v1);
                unpack2(acc[r][1], v2, v3);
                float* dst = Ash + (i0 + r) * ASTR + j0;
                dst[0] = v0; dst[1] = v1; dst[2] = v2; dst[3] = v3;
            }
        }
    }
    __syncthreads();

    if (tid < 128) diag_s[tid] = Ash[tid * ASTR + tid];
    __syncthreads();

    // ---- elementwise transform on lower triangle (+ mirror to upper) ----
    {
        const float th3 = theta[3], th4 = theta[4], th5 = theta[5];
        const float ls   = __expf(th5) * 1.7320508075688772f;  // sqrt(2*1.5)
        const float ils2 = 1.0f / (ls * ls);
        const float sg   = __expf(__logf(scales[n]) * th4 + th3);
        const float sig2 = sg * sg;
        const float inug = 1.0f / nug[n];
        for (int L = tid; L < 8256; L += NTH) {
            int i = (int)((sqrtf(8.0f * (float)L + 1.0f) - 1.0f) * 0.5f);
            while ((i + 1) * (i + 2) / 2 <= L) ++i;
            while (i * (i + 1) / 2 > L) --i;
            int j = L - i * (i + 1) / 2;
            float lin = Ash[i * ASTR + j];
            float sq  = (diag_s[i] + diag_s[j] - 2.0f * lin) * ils2;
            float d   = sqrtf(fmaxf(sq, 0.0f));
            float s3  = 1.7320508075688772f * d;
            float mat = (1.0f + s3) * __expf(-s3);
            float val = (lin + sig2 * mat) * inug;
            if (i == j) val += 1.0f;
            Ash[i * ASTR + j] = val;
            Ash[j * ASTR + i] = val;
        }
    }
    __syncthreads();

    // ---- write g (full symmetric matrix), coalesced ----
    for (int idx = tid; idx < 16384; idx += NTH)
        gout[idx] = Ash[(idx >> 7) * ASTR + (idx & 127)];
    __syncthreads();

    // ---- blocked Cholesky, NB=32, in place on lower triangle of Ash ----
    const int lane = tid & 31, wid = tid >> 5;
    for (int p = 0; p < 4; ++p) {
        const int pb = p * 32;

        // (a) 32x32 diagonal block: warp 0, fully register/shuffle resident
        if (wid == 0) {
            float a[32];
            #pragma unroll
            for (int c = 0; c < 32; ++c)
                a[c] = (c <= lane) ? Ash[(pb + lane) * ASTR + pb + c] : 0.0f;
            #pragma unroll
            for (int j = 0; j < 32; ++j) {
                float ajj = __shfl_sync(0xffffffffu, a[j], j);
                float rd  = rsqrtf(ajj);
                if (lane == j)      { a[j] = ajj * rd; invd_s[j] = rd; }
                else if (lane > j)  { a[j] *= rd; }
                float t = a[j];
                #pragma unroll
                for (int k2 = j + 1; k2 < 32; ++k2) {
                    float lkj = __shfl_sync(0xffffffffu, a[j], k2);
                    if (lane >= k2) a[k2] -= t * lkj;
                }
            }
            #pragma unroll
            for (int c = 0; c < 32; ++c)
                if (c <= lane) Ash[(pb + lane) * ASTR + pb + c] = a[c];
        }
        __syncthreads();

        const int q = pb + 32;
        const int mrows = 128 - q;
        if (mrows > 0) {
            // (b) TRSM: row-per-thread, row fully in registers, L00 via smem broadcast
            if (tid < mrows) {
                const int row = q + tid;
                float b[32];
                #pragma unroll
                for (int c = 0; c < 32; ++c) b[c] = Ash[row * ASTR + pb + c];
                #pragma unroll
                for (int j = 0; j < 32; ++j) {
                    b[j] *= invd_s[j];
                    float bj = b[j];
                    #pragma unroll
                    for (int k2 = j + 1; k2 < 32; ++k2)
                        b[k2] -= bj * Ash[(pb + k2) * ASTR + pb + j];
                }
                #pragma unroll
                for (int c = 0; c < 32; ++c) Ash[row * ASTR + pb + c] = b[c];
            }
            __syncthreads();

            // (c) Schur: A22 -= L21 L21^T, lower triangle, 4x4 register microtiles
            const int G = mrows >> 2;
            const int T = G * (G + 1) / 2;
            for (int t = tid; t < T; t += NTH) {
                int mi = (int)((sqrtf(8.0f * (float)t + 1.0f) - 1.0f) * 0.5f);
                while ((mi + 1) * (mi + 2) / 2 <= t) ++mi;
                while (mi * (mi + 1) / 2 > t) --mi;
                int mj = t - mi * (mi + 1) / 2;
                const int i0 = q + mi * 4, j0 = q + mj * 4;
                float acc[4][4];
                #pragma unroll
                for (int r = 0; r < 4; ++r)
                    #pragma unroll
                    for (int c = 0; c < 4; ++c) acc[r][c] = 0.0f;
                #pragma unroll 8
                for (int k2 = 0; k2 < 32; ++k2) {
                    float av[4], bv[4];
                    #pragma unroll
                    for (int r = 0; r < 4; ++r) av[r] = Ash[(i0 + r) * ASTR + pb + k2];
                    #pragma unroll
                    for (int c = 0; c < 4; ++c) bv[c] = Ash[(j0 + c) * ASTR + pb + k2];
                    #pragma unroll
                    for (int r = 0; r < 4; ++r)
                        #pragma unroll
                        for (int c = 0; c < 4; ++c)
                            acc[r][c] += av[r] * bv[c];
                }
                #pragma unroll
                for (int r = 0; r < 4; ++r)
                    #pragma unroll
                    for (int c = 0; c < 4; ++c)
                        Ash[(i0 + r) * ASTR + j0 + c] -= acc[r][c];
            }
        }
        __syncthreads();
    }

    // ---- write chol (lower; zeros above) ----
    for (int idx = tid; idx < 16384; idx += NTH) {
        int i = idx >> 7, j = idx & 127;
        cout[idx] = (j <= i) ? Ash[i * ASTR + j] : 0.0f;
    }
}

extern "C" void kernel_launch(void* const* d_in, const int* in_sizes, int n_in,
                              void* d_out, int out_size)
{
    const float* aug    = (const float*)d_in[0];
    const float* theta  = (const float*)d_in[1];
    const float* scales = (const float*)d_in[2];
    const float* nug    = (const float*)d_in[3];
    const int*   bidx   = (const int*)d_in[4];
    const int n_loc = in_sizes[2];

    const size_t smem = SMEM_FLOATS * sizeof(float);
    cudaFuncSetAttribute(tmap_kernel, cudaFuncAttributeMaxDynamicSharedMemorySize, (int)smem);
    tmap_kernel<<<n_loc, NTH, smem>>>(aug, theta, scales, nug, bidx, (float*)d_out, n_loc);
}

// round 7
// speedup vs baseline: 1.2289x; 1.2289x over previous
#include <cuda_runtime.h>
#include <math.h>

#define NREP 128
#define MNBR 48
#define NTH  256
#define ASTR 129          // A matrix shared stride (odd -> conflict-free column walks)
#define XSTR 130          // xsT shared stride (even -> float2 aligned)

// shared layout (float offsets). XT ALIASES the start of Ash (rows 0..48):
// gram tiles touching rows>=64 are stored while XT is live; tile (0,0) is
// register-staged and stored after all XT reads complete.
#define OFF_A    0
#define OFF_SCAL 16512    // 128*129
#define OFF_DIAG 16560
#define OFF_INVD 16688
#define SMEM_FLOATS 16720 // ~65.3 KB  -> 3 CTAs/SM

__device__ __forceinline__ unsigned long long dup2(float x) {
    unsigned long long r;
    asm("mov.b64 %0, {%1, %1};" : "=l"(r) : "r"(__float_as_uint(x)));
    return r;
}
__device__ __forceinline__ unsigned long long pack2(float x, float y) {
    unsigned long long r;
    asm("mov.b64 %0, {%1, %2};" : "=l"(r) : "r"(__float_as_uint(x)), "r"(__float_as_uint(y)));
    return r;
}
__device__ __forceinline__ void unpack2(unsigned long long v, float &x, float &y) {
    unsigned lo, hi;
    asm("mov.b64 {%0, %1}, %2;" : "=r"(lo), "=r"(hi) : "l"(v));
    x = __uint_as_float(lo); y = __uint_as_float(hi);
}
// packed dual-FMA (sm_103a FFMA2) -- 2x fp32 throughput vs scalar FFMA
__device__ __forceinline__ void ffma2(unsigned long long &d, unsigned long long a, unsigned long long b) {
    asm("fma.rn.f32x2 %0, %1, %2, %3;" : "=l"(d) : "l"(a), "l"(b), "l"(d));
}

// one 64x64-tile 4x4 microtile gram accumulation (K=48) into packed f32x2 regs
__device__ __forceinline__ void gram_tile(const float* __restrict__ XT, int i0, int j0,
                                          unsigned long long acc[4][2]) {
    #pragma unroll
    for (int r = 0; r < 4; ++r) { acc[r][0] = 0ull; acc[r][1] = 0ull; }
    #pragma unroll 8
    for (int k = 0; k < MNBR; ++k) {
        const float2* row = (const float2*)(XT + k * XSTR);
        float2 a01 = row[i0 >> 1];
        float2 a23 = row[(i0 >> 1) + 1];
        float2 b01 = row[j0 >> 1];
        float2 b23 = row[(j0 >> 1) + 1];
        unsigned long long bu0 = pack2(b01.x, b01.y);
        unsigned long long bu1 = pack2(b23.x, b23.y);
        unsigned long long a0 = dup2(a01.x), a1 = dup2(a01.y);
        unsigned long long a2 = dup2(a23.x), a3 = dup2(a23.y);
        ffma2(acc[0][0], a0, bu0); ffma2(acc[0][1], a0, bu1);
        ffma2(acc[1][0], a1, bu0); ffma2(acc[1][1], a1, bu1);
        ffma2(acc[2][0], a2, bu0); ffma2(acc[2][1], a2, bu1);
        ffma2(acc[3][0], a3, bu0); ffma2(acc[3][1], a3, bu1);
    }
}

__device__ __forceinline__ void gram_store(float* __restrict__ Ash, int i0, int j0,
                                           unsigned long long acc[4][2]) {
    #pragma unroll
    for (int r = 0; r < 4; ++r) {
        float v0, v1, v2, v3;
        unpack2(acc[r][0], v0, v1);
        unpack2(acc[r][1], v2, v3);
        float* dst = Ash + (i0 + r) * ASTR + j0;
        dst[0] = v0; dst[1] = v1; dst[2] = v2; dst[3] = v3;
    }
}

extern "C" __global__ void __launch_bounds__(NTH, 3)
tmap_kernel(const float* __restrict__ aug,
            const float* __restrict__ theta,
            const float* __restrict__ scales,
            const float* __restrict__ nug,
            const int*   __restrict__ bidx,
            float* __restrict__ out,
            int n_loc)
{
    extern __shared__ float sm[];
    float* Ash    = sm + OFF_A;
    float* XT     = sm + OFF_A;      // aliased with Ash rows 0..48
    float* scal_s = sm + OFF_SCAL;
    float* diag_s = sm + OFF_DIAG;
    float* invd_s = sm + OFF_INVD;

    const int n   = blockIdx.x;
    const int tid = threadIdx.x;
    float* gout = out + (size_t)n * 16384;
    float* cout = out + (size_t)n_loc * 16384 + (size_t)n * 16384;

    // batch_idx == 0  ->  g = I, chol = I
    if (bidx[n] == 0) {
        for (int q4 = tid; q4 < 4096; q4 += NTH) {
            int idx = q4 * 4;
            int i = idx >> 7, j = idx & 127;
            float4 v = make_float4(i == j ? 1.f : 0.f, i == j + 1 ? 1.f : 0.f,
                                   i == j + 2 ? 1.f : 0.f, i == j + 3 ? 1.f : 0.f);
            ((float4*)gout)[q4] = v;
            ((float4*)cout)[q4] = v;
        }
        return;
    }

    // ---- per-column scaling: scal_k = exp(-0.5*k*exp(theta2)), k=1..48 ----
    const float e2 = __expf(theta[2]);
    if (tid < MNBR) scal_s[tid] = __expf(-0.5f * (float)(tid + 1) * e2);
    __syncthreads();

    // ---- load xs transposed into shared: XT[k][r] = aug[r,n,k+1]*scal_k ----
    for (int idx = tid; idx < NREP * MNBR; idx += NTH) {
        int r = idx / MNBR, k = idx - r * MNBR;
        float v = aug[((size_t)r * n_loc + n) * (MNBR + 1) + 1 + k];
        if (v != v) v = 0.0f;  // NaN -> 0
        XT[k * XSTR + r] = v * scal_s[k];
    }
    __syncthreads();

    // ---- symmetric gram G = xs * xs^T : 3 lower 64x64 tiles ----
    // tiles (1,0),(1,1) live in Ash rows 64..127 (disjoint from XT) -> store now.
    // tile (0,0) overlaps XT -> register-stage, sync, then store.
    {
        const int tx = tid & 15, ty = tid >> 4;
        unsigned long long acc[4][2];
        gram_tile(XT, 64 + ty * 4, tx * 4, acc);
        gram_store(Ash, 64 + ty * 4, tx * 4, acc);
        gram_tile(XT, 64 + ty * 4, 64 + tx * 4, acc);
        gram_store(Ash, 64 + ty * 4, 64 + tx * 4, acc);
        gram_tile(XT, ty * 4, tx * 4, acc);
        __syncthreads();      // all XT reads complete before overwriting rows 0..48
        gram_store(Ash, ty * 4, tx * 4, acc);
    }
    __syncthreads();

    if (tid < 128) diag_s[tid] = Ash[tid * ASTR + tid];
    __syncthreads();

    // ---- elementwise transform on lower triangle (+ mirror to upper) ----
    {
        const float th3 = theta[3], th4 = theta[4], th5 = theta[5];
        const float ls   = __expf(th5) * 1.7320508075688772f;  // sqrt(2*1.5)
        const float ils2 = 1.0f / (ls * ls);
        const float sg   = __expf(__logf(scales[n]) * th4 + th3);
        const float sig2 = sg * sg;
        const float inug = 1.0f / nug[n];
        for (int L = tid; L < 8256; L += NTH) {
            int i = (int)((sqrtf(8.0f * (float)L + 1.0f) - 1.0f) * 0.5f);
            while ((i + 1) * (i + 2) / 2 <= L) ++i;
            while (i * (i + 1) / 2 > L) --i;
            int j = L - i * (i + 1) / 2;
            float lin = Ash[i * ASTR + j];
            float sq  = (diag_s[i] + diag_s[j] - 2.0f * lin) * ils2;
            float d   = sqrtf(fmaxf(sq, 0.0f));
            float s3  = 1.7320508075688772f * d;
            float mat = (1.0f + s3) * __expf(-s3);
            float val = (lin + sig2 * mat) * inug;
            if (i == j) val += 1.0f;
            Ash[i * ASTR + j] = val;
            Ash[j * ASTR + i] = val;
        }
    }
    __syncthreads();

    // ---- write g (full symmetric matrix), float4 coalesced ----
    for (int q4 = tid; q4 < 4096; q4 += NTH) {
        int idx = q4 * 4;
        const float* src = Ash + (idx >> 7) * ASTR + (idx & 127);
        ((float4*)gout)[q4] = make_float4(src[0], src[1], src[2], src[3]);
    }
    __syncthreads();

    // ---- blocked Cholesky, NB=32, in place on lower triangle of Ash ----
    const int lane = tid & 31, wid = tid >> 5;
    for (int p = 0; p < 4; ++p) {
        const int pb = p * 32;

        // (a) 32x32 diagonal block: warp 0, fully register/shuffle resident
        if (wid == 0) {
            float a[32];
            #pragma unroll
            for (int c = 0; c < 32; ++c)
                a[c] = (c <= lane) ? Ash[(pb + lane) * ASTR + pb + c] : 0.0f;
            #pragma unroll
            for (int j = 0; j < 32; ++j) {
                float ajj = __shfl_sync(0xffffffffu, a[j], j);
                float rd  = rsqrtf(ajj);
                if (lane == j)      { a[j] = ajj * rd; invd_s[j] = rd; }
                else if (lane > j)  { a[j] *= rd; }
                float t = a[j];
                #pragma unroll
                for (int k2 = j + 1; k2 < 32; ++k2) {
                    float lkj = __shfl_sync(0xffffffffu, a[j], k2);
                    if (lane >= k2) a[k2] -= t * lkj;
                }
            }
            #pragma unroll
            for (int c = 0; c < 32; ++c)
                if (c <= lane) Ash[(pb + lane) * ASTR + pb + c] = a[c];
        }
        __syncthreads();

        const int q = pb + 32;
        const int mrows = 128 - q;
        if (mrows > 0) {
            // (b) TRSM: row-per-thread, row fully in registers, L00 via smem broadcast
            if (tid < mrows) {
                const int row = q + tid;
                float b[32];
                #pragma unroll
                for (int c = 0; c < 32; ++c) b[c] = Ash[row * ASTR + pb + c];
                #pragma unroll
                for (int j = 0; j < 32; ++j) {
                    b[j] *= invd_s[j];
                    float bj = b[j];
                    #pragma unroll
                    for (int k2 = j + 1; k2 < 32; ++k2)
                        b[k2] -= bj * Ash[(pb + k2) * ASTR + pb + j];
                }
                #pragma unroll
                for (int c = 0; c < 32; ++c) Ash[row * ASTR + pb + c] = b[c];
            }
            __syncthreads();

            // (c) Schur: A22 -= L21 L21^T, lower triangle, 4x4 register microtiles
            const int G = mrows >> 2;
            const int T = G * (G + 1) / 2;
            for (int t = tid; t < T; t += NTH) {
                int mi = (int)((sqrtf(8.0f * (float)t + 1.0f) - 1.0f) * 0.5f);
                while ((mi + 1) * (mi + 2) / 2 <= t) ++mi;
                while (mi * (mi + 1) / 2 > t) --mi;
                int mj = t - mi * (mi + 1) / 2;
                const int i0 = q + mi * 4, j0 = q + mj * 4;
                float acc[4][4];
                #pragma unroll
                for (int r = 0; r < 4; ++r)
                    #pragma unroll
                    for (int c = 0; c < 4; ++c) acc[r][c] = 0.0f;
                #pragma unroll 8
                for (int k2 = 0; k2 < 32; ++k2) {
                    float av[4], bv[4];
                    #pragma unroll
                    for (int r = 0; r < 4; ++r) av[r] = Ash[(i0 + r) * ASTR + pb + k2];
                    #pragma unroll
                    for (int c = 0; c < 4; ++c) bv[c] = Ash[(j0 + c) * ASTR + pb + k2];
                    #pragma unroll
                    for (int r = 0; r < 4; ++r)
                        #pragma unroll
                        for (int c = 0; c < 4; ++c)
                            acc[r][c] += av[r] * bv[c];
                }
                #pragma unroll
                for (int r = 0; r < 4; ++r)
                    #pragma unroll
                    for (int c = 0; c < 4; ++c)
                        Ash[(i0 + r) * ASTR + j0 + c] -= acc[r][c];
            }
        }
        __syncthreads();
    }

    // ---- write chol (lower; zeros above), float4 coalesced ----
    for (int q4 = tid; q4 < 4096; q4 += NTH) {
        int idx = q4 * 4;
        int i = idx >> 7, j = idx & 127;
        const float* src = Ash + i * ASTR + j;
        float4 v;
        v.x = (j     <= i) ? src[0] : 0.0f;
        v.y = (j + 1 <= i) ? src[1] : 0.0f;
        v.z = (j + 2 <= i) ? src[2] : 0.0f;
        v.w = (j + 3 <= i) ? src[3] : 0.0f;
        ((float4*)cout)[q4] = v;
    }
}

extern "C" void kernel_launch(void* const* d_in, const int* in_sizes, int n_in,
                              void* d_out, int out_size)
{
    const float* aug    = (const float*)d_in[0];
    const float* theta  = (const float*)d_in[1];
    const float* scales = (const float*)d_in[2];
    const float* nug    = (const float*)d_in[3];
    const int*   bidx   = (const int*)d_in[4];
    const int n_loc = in_sizes[2];

    const size_t smem = SMEM_FLOATS * sizeof(float);
    cudaFuncSetAttribute(tmap_kernel, cudaFuncAttributeMaxDynamicSharedMemorySize, (int)smem);
    tmap_kernel<<<n_loc, NTH, smem>>>(aug, theta, scales, nug, bidx, (float*)d_out, n_loc);
}

// round 8
// speedup vs baseline: 1.2423x; 1.0110x over previous
#include <cuda_runtime.h>
#include <math.h>

#define NREP 128
#define MNBR 48
#define NTH  256
#define ASTR 132          // multiple of 4 -> every row 16B-aligned -> float4 LDS/STS
#define XSTR 132

// shared layout (float offsets). XT ALIASES Ash rows 0..47.
#define OFF_A    0
#define OFF_SCAL 16896    // 128*132
#define OFF_DIAG 16944
#define OFF_INVD 17072
#define SMEM_FLOATS 17104 // 66.8 KB -> 3 CTAs/SM

__device__ __forceinline__ unsigned long long dup2(float x) {
    unsigned long long r;
    asm("mov.b64 %0, {%1, %1};" : "=l"(r) : "r"(__float_as_uint(x)));
    return r;
}
__device__ __forceinline__ unsigned long long pack2(float x, float y) {
    unsigned long long r;
    asm("mov.b64 %0, {%1, %2};" : "=l"(r) : "r"(__float_as_uint(x)), "r"(__float_as_uint(y)));
    return r;
}
__device__ __forceinline__ void unpack2(unsigned long long v, float &x, float &y) {
    unsigned lo, hi;
    asm("mov.b64 {%0, %1}, %2;" : "=r"(lo), "=r"(hi) : "l"(v));
    x = __uint_as_float(lo); y = __uint_as_float(hi);
}
// packed dual-FMA (sm_103a FFMA2) -- 2x fp32 throughput vs scalar FFMA
__device__ __forceinline__ void ffma2(unsigned long long &d, unsigned long long a, unsigned long long b) {
    asm("fma.rn.f32x2 %0, %1, %2, %3;" : "=l"(d) : "l"(a), "l"(b), "l"(d));
}

// one 64x64-tile 4x4 microtile gram accumulation (K=48) into packed f32x2 regs
__device__ __forceinline__ void gram_tile(const float* __restrict__ XT, int i0, int j0,
                                          unsigned long long acc[4][2]) {
    #pragma unroll
    for (int r = 0; r < 4; ++r) { acc[r][0] = 0ull; acc[r][1] = 0ull; }
    #pragma unroll 8
    for (int k = 0; k < MNBR; ++k) {
        const float* row = XT + k * XSTR;
        float4 a4 = *(const float4*)(row + i0);
        float4 b4 = *(const float4*)(row + j0);
        unsigned long long bu0 = pack2(b4.x, b4.y);
        unsigned long long bu1 = pack2(b4.z, b4.w);
        unsigned long long a0 = dup2(a4.x), a1 = dup2(a4.y);
        unsigned long long a2 = dup2(a4.z), a3 = dup2(a4.w);
        ffma2(acc[0][0], a0, bu0); ffma2(acc[0][1], a0, bu1);
        ffma2(acc[1][0], a1, bu0); ffma2(acc[1][1], a1, bu1);
        ffma2(acc[2][0], a2, bu0); ffma2(acc[2][1], a2, bu1);
        ffma2(acc[3][0], a3, bu0); ffma2(acc[3][1], a3, bu1);
    }
}

__device__ __forceinline__ void gram_store(float* __restrict__ Ash, int i0, int j0,
                                           unsigned long long acc[4][2]) {
    #pragma unroll
    for (int r = 0; r < 4; ++r) {
        float4 v;
        unpack2(acc[r][0], v.x, v.y);
        unpack2(acc[r][1], v.z, v.w);
        *(float4*)(Ash + (i0 + r) * ASTR + j0) = v;
    }
}

extern "C" __global__ void __launch_bounds__(NTH, 3)
tmap_kernel(const float* __restrict__ aug,
            const float* __restrict__ theta,
            const float* __restrict__ scales,
            const float* __restrict__ nug,
            const int*   __restrict__ bidx,
            float* __restrict__ out,
            int n_loc)
{
    extern __shared__ float sm[];
    float* Ash    = sm + OFF_A;
    float* XT     = sm + OFF_A;      // aliased with Ash rows 0..47
    float* scal_s = sm + OFF_SCAL;
    float* diag_s = sm + OFF_DIAG;
    float* invd_s = sm + OFF_INVD;

    const int n   = blockIdx.x;
    const int tid = threadIdx.x;
    float* gout = out + (size_t)n * 16384;
    float* cout = out + (size_t)n_loc * 16384 + (size_t)n * 16384;

    // batch_idx == 0  ->  g = I, chol = I
    if (bidx[n] == 0) {
        for (int q4 = tid; q4 < 4096; q4 += NTH) {
            int idx = q4 * 4;
            int i = idx >> 7, j = idx & 127;
            float4 v = make_float4(i == j ? 1.f : 0.f, i == j + 1 ? 1.f : 0.f,
                                   i == j + 2 ? 1.f : 0.f, i == j + 3 ? 1.f : 0.f);
            ((float4*)gout)[q4] = v;
            ((float4*)cout)[q4] = v;
        }
        return;
    }

    // ---- per-column scaling: scal_k = exp(-0.5*k*exp(theta2)), k=1..48 ----
    const float e2 = __expf(theta[2]);
    if (tid < MNBR) scal_s[tid] = __expf(-0.5f * (float)(tid + 1) * e2);
    __syncthreads();

    // ---- load xs transposed into shared: XT[k][r] = aug[r,n,k+1]*scal_k ----
    for (int idx = tid; idx < NREP * MNBR; idx += NTH) {
        int r = idx / MNBR, k = idx - r * MNBR;
        float v = aug[((size_t)r * n_loc + n) * (MNBR + 1) + 1 + k];
        if (v != v) v = 0.0f;  // NaN -> 0
        XT[k * XSTR + r] = v * scal_s[k];
    }
    __syncthreads();

    // ---- symmetric gram G = xs * xs^T : 3 lower 64x64 tiles ----
    // tiles (1,0),(1,1) live in Ash rows 64..127 (disjoint from XT) -> store now.
    // tile (0,0) overlaps XT -> register-stage, sync, then store.
    {
        const int tx = tid & 15, ty = tid >> 4;
        unsigned long long acc[4][2];
        gram_tile(XT, 64 + ty * 4, tx * 4, acc);
        gram_store(Ash, 64 + ty * 4, tx * 4, acc);
        gram_tile(XT, 64 + ty * 4, 64 + tx * 4, acc);
        gram_store(Ash, 64 + ty * 4, 64 + tx * 4, acc);
        gram_tile(XT, ty * 4, tx * 4, acc);
        __syncthreads();      // all XT reads complete before overwriting rows 0..47
        gram_store(Ash, ty * 4, tx * 4, acc);
    }
    __syncthreads();

    if (tid < 128) diag_s[tid] = Ash[tid * ASTR + tid];
    __syncthreads();

    // ---- elementwise transform on lower triangle (+ mirror to upper) ----
    // lower-triangle decode via 64x129 rectangle: row u pairs with row 127-u.
    {
        const float th3 = theta[3], th4 = theta[4], th5 = theta[5];
        const float ls   = __expf(th5) * 1.7320508075688772f;  // sqrt(2*1.5)
        const float ils2 = 1.0f / (ls * ls);
        const float sg   = __expf(__logf(scales[n]) * th4 + th3);
        const float sig2 = sg * sg;
        const float inug = 1.0f / nug[n];
        for (int L = tid; L < 8256; L += NTH) {
            int u = L / 129;
            int v = L - u * 129;
            int i, j;
            if (v <= u) { i = u; j = v; }
            else        { i = 127 - u; j = v - u - 1; }
            float lin = Ash[i * ASTR + j];
            float sq  = (diag_s[i] + diag_s[j] - 2.0f * lin) * ils2;
            float d   = sqrtf(fmaxf(sq, 0.0f));
            float s3  = 1.7320508075688772f * d;
            float mat = (1.0f + s3) * __expf(-s3);
            float val = (lin + sig2 * mat) * inug;
            if (i == j) val += 1.0f;
            Ash[i * ASTR + j] = val;
            Ash[j * ASTR + i] = val;
        }
    }
    __syncthreads();

    // ---- write g (full symmetric matrix), float4 coalesced ----
    for (int q4 = tid; q4 < 4096; q4 += NTH) {
        int idx = q4 * 4;
        ((float4*)gout)[q4] = *(const float4*)(Ash + (idx >> 7) * ASTR + (idx & 127));
    }
    __syncthreads();

    // ---- blocked Cholesky, NB=32, in place on lower triangle of Ash ----
    const int lane = tid & 31, wid = tid >> 5;
    for (int p = 0; p < 4; ++p) {
        const int pb = p * 32;

        // (a) 32x32 diagonal block: warp 0, fully register/shuffle resident.
        // Vector loads/stores; within-block upper elements are dead after the
        // g write, so storing zeros there is safe.
        if (wid == 0) {
            float a[32];
            #pragma unroll
            for (int cc = 0; cc < 8; ++cc) {
                float4 v = *(const float4*)(Ash + (pb + lane) * ASTR + pb + 4 * cc);
                a[4*cc+0] = (4*cc+0 <= lane) ? v.x : 0.0f;
                a[4*cc+1] = (4*cc+1 <= lane) ? v.y : 0.0f;
                a[4*cc+2] = (4*cc+2 <= lane) ? v.z : 0.0f;
                a[4*cc+3] = (4*cc+3 <= lane) ? v.w : 0.0f;
            }
            #pragma unroll
            for (int j = 0; j < 32; ++j) {
                float ajj = __shfl_sync(0xffffffffu, a[j], j);
                float rd  = rsqrtf(ajj);
                if (lane == j)      { a[j] = ajj * rd; invd_s[j] = rd; }
                else if (lane > j)  { a[j] *= rd; }
                float t = a[j];
                #pragma unroll
                for (int k2 = j + 1; k2 < 32; ++k2) {
                    float lkj = __shfl_sync(0xffffffffu, a[j], k2);
                    if (lane >= k2) a[k2] -= t * lkj;
                }
            }
            #pragma unroll
            for (int cc = 0; cc < 8; ++cc) {
                float4 v = make_float4(a[4*cc+0], a[4*cc+1], a[4*cc+2], a[4*cc+3]);
                *(float4*)(Ash + (pb + lane) * ASTR + pb + 4 * cc) = v;
            }
        }
        __syncthreads();

        const int q = pb + 32;
        const int mrows = 128 - q;
        if (mrows > 0) {
            // (b) TRSM: row-per-thread, row fully in registers, L00 via smem broadcast
            if (tid < mrows) {
                const int row = q + tid;
                float b[32];
                #pragma unroll
                for (int cc = 0; cc < 8; ++cc) {
                    float4 v = *(const float4*)(Ash + row * ASTR + pb + 4 * cc);
                    b[4*cc+0] = v.x; b[4*cc+1] = v.y; b[4*cc+2] = v.z; b[4*cc+3] = v.w;
                }
                #pragma unroll
                for (int j = 0; j < 32; ++j) {
                    b[j] *= invd_s[j];
                    float bj = b[j];
                    #pragma unroll
                    for (int k2 = j + 1; k2 < 32; ++k2)
                        b[k2] -= bj * Ash[(pb + k2) * ASTR + pb + j];
                }
                #pragma unroll
                for (int cc = 0; cc < 8; ++cc) {
                    float4 v = make_float4(b[4*cc+0], b[4*cc+1], b[4*cc+2], b[4*cc+3]);
                    *(float4*)(Ash + row * ASTR + pb + 4 * cc) = v;
                }
            }
            __syncthreads();

            // (c) Schur: A22 -= L21 L21^T, lower triangle, 4x4 register microtiles,
            // float4 k-chunks + packed FFMA2.
            const int G = mrows >> 2;              // 24, 16, 8 (even)
            const int T = (G / 2) * (G + 1);       // = G(G+1)/2
            for (int t = tid; t < T; t += NTH) {
                int u = t / (G + 1);
                int v = t - u * (G + 1);
                int mi, mj;
                if (v <= u) { mi = u; mj = v; }
                else        { mi = G - 1 - u; mj = v - u - 1; }
                const int i0 = q + mi * 4, j0 = q + mj * 4;
                unsigned long long acc2[4][2];
                #pragma unroll
                for (int r = 0; r < 4; ++r) { acc2[r][0] = 0ull; acc2[r][1] = 0ull; }
                #pragma unroll
                for (int kk = 0; kk < 32; kk += 4) {
                    float4 av[4], bv[4];
                    #pragma unroll
                    for (int r = 0; r < 4; ++r)
                        av[r] = *(const float4*)(Ash + (i0 + r) * ASTR + pb + kk);
                    #pragma unroll
                    for (int c = 0; c < 4; ++c)
                        bv[c] = *(const float4*)(Ash + (j0 + c) * ASTR + pb + kk);
                    // k component x
                    {
                        unsigned long long b0 = pack2(bv[0].x, bv[1].x), b1 = pack2(bv[2].x, bv[3].x);
                        unsigned long long a0 = dup2(av[0].x), a1 = dup2(av[1].x), a2 = dup2(av[2].x), a3 = dup2(av[3].x);
                        ffma2(acc2[0][0], a0, b0); ffma2(acc2[0][1], a0, b1);
                        ffma2(acc2[1][0], a1, b0); ffma2(acc2[1][1], a1, b1);
                        ffma2(acc2[2][0], a2, b0); ffma2(acc2[2][1], a2, b1);
                        ffma2(acc2[3][0], a3, b0); ffma2(acc2[3][1], a3, b1);
                    }
                    // k component y
                    {
                        unsigned long long b0 = pack2(bv[0].y, bv[1].y), b1 = pack2(bv[2].y, bv[3].y);
                        unsigned long long a0 = dup2(av[0].y), a1 = dup2(av[1].y), a2 = dup2(av[2].y), a3 = dup2(av[3].y);
                        ffma2(acc2[0][0], a0, b0); ffma2(acc2[0][1], a0, b1);
                        ffma2(acc2[1][0], a1, b0); ffma2(acc2[1][1], a1, b1);
                        ffma2(acc2[2][0], a2, b0); ffma2(acc2[2][1], a2, b1);
                        ffma2(acc2[3][0], a3, b0); ffma2(acc2[3][1], a3, b1);
                    }
                    // k component z
                    {
                        unsigned long long b0 = pack2(bv[0].z, bv[1].z), b1 = pack2(bv[2].z, bv[3].z);
                        unsigned long long a0 = dup2(av[0].z), a1 = dup2(av[1].z), a2 = dup2(av[2].z), a3 = dup2(av[3].z);
                        ffma2(acc2[0][0], a0, b0); ffma2(acc2[0][1], a0, b1);
                        ffma2(acc2[1][0], a1, b0); ffma2(acc2[1][1], a1, b1);
                        ffma2(acc2[2][0], a2, b0); ffma2(acc2[2][1], a2, b1);
                        ffma2(acc2[3][0], a3, b0); ffma2(acc2[3][1], a3, b1);
                    }
                    // k component w
                    {
                        unsigned long long b0 = pack2(bv[0].w, bv[1].w), b1 = pack2(bv[2].w, bv[3].w);
                        unsigned long long a0 = dup2(av[0].w), a1 = dup2(av[1].w), a2 = dup2(av[2].w), a3 = dup2(av[3].w);
                        ffma2(acc2[0][0], a0, b0); ffma2(acc2[0][1], a0, b1);
                        ffma2(acc2[1][0], a1, b0); ffma2(acc2[1][1], a1, b1);
                        ffma2(acc2[2][0], a2, b0); ffma2(acc2[2][1], a2, b1);
                        ffma2(acc2[3][0], a3, b0); ffma2(acc2[3][1], a3, b1);
                    }
                }
                #pragma unroll
                for (int r = 0; r < 4; ++r) {
                    float s0, s1, s2, s3;
                    unpack2(acc2[r][0], s0, s1);
                    unpack2(acc2[r][1], s2, s3);
                    float4* dst = (float4*)(Ash + (i0 + r) * ASTR + j0);
                    float4 d = *dst;
                    d.x -= s0; d.y -= s1; d.z -= s2; d.w -= s3;
                    *dst = d;
                }
            }
        }
        __syncthreads();
    }

    // ---- write chol (lower; zeros above), float4 coalesced ----
    for (int q4 = tid; q4 < 4096; q4 += NTH) {
        int idx = q4 * 4;
        int i = idx >> 7, j = idx & 127;
        float4 s = *(const float4*)(Ash + i * ASTR + j);
        float4 v;
        v.x = (j     <= i) ? s.x : 0.0f;
        v.y = (j + 1 <= i) ? s.y : 0.0f;
        v.z = (j + 2 <= i) ? s.z : 0.0f;
        v.w = (j + 3 <= i) ? s.w : 0.0f;
        ((float4*)cout)[q4] = v;
    }
}

extern "C" void kernel_launch(void* const* d_in, const int* in_sizes, int n_in,
                              void* d_out, int out_size)
{
    const float* aug    = (const float*)d_in[0];
    const float* theta  = (const float*)d_in[1];
    const float* scales = (const float*)d_in[2];
    const float* nug    = (const float*)d_in[3];
    const int*   bidx   = (const int*)d_in[4];
    const int n_loc = in_sizes[2];

    const size_t smem = SMEM_FLOATS * sizeof(float);
    cudaFuncSetAttribute(tmap_kernel, cudaFuncAttributeMaxDynamicSharedMemorySize, (int)smem);
    tmap_kernel<<<n_loc, NTH, smem>>>(aug, theta, scales, nug, bidx, (float*)d_out, n_loc);
}